// round 2
// baseline (speedup 1.0000x reference)
#include <cuda_runtime.h>
#include <cuda_bf16.h>
#include <math.h>

// Problem dims
#define BSZ   256
#define SIG   64
#define LATD  256
#define ENCH  256
#define DECH  512
#define RHSH  512
#define TSTEPS 200

#define NBLK  128   // persistent ODE grid (<= 148 SMs, 1 block/SM via smem)

// ---------------- scratch (device globals; no allocation) ----------------
__device__ float g_z[TSTEPS * BSZ * LATD];        // pred_z, 52.4 MB
__device__ float g_h1[BSZ * RHSH];
__device__ float g_h2[BSZ * RHSH];
__device__ float g_kst[3 * BSZ * LATD];           // k1,k2,k3
__device__ float g_x0[3 * BSZ * ENCH];
__device__ float g_x1[2 * BSZ * ENCH];
__device__ float g_A0[3 * BSZ * 256];
__device__ float g_A1[2 * BSZ * 1024];
__device__ float g_A2[BSZ * 768];
__device__ float g_Wc0[ENCH * 256];
__device__ float g_Wc1[ENCH * 1024];
__device__ float g_Wc2[LATD * 768];
__device__ float g_bc0[ENCH];
__device__ float g_bc1[ENCH];
__device__ float g_bc2[LATD];
__device__ float g_hd1[(size_t)TSTEPS * BSZ * DECH];
__device__ float g_hd2[(size_t)TSTEPS * BSZ * DECH];

// ---------------- software grid barrier ----------------
__device__ unsigned g_arr = 0;
__device__ volatile unsigned g_gen = 0;

__device__ __forceinline__ void gsync(unsigned& lg)
{
    __threadfence();           // release: make this thread's gmem writes visible
    __syncthreads();
    if (threadIdx.x == 0) {
        const unsigned ticket = atomicAdd(&g_arr, 1u);
        if (ticket == gridDim.x - 1) {
            atomicExch(&g_arr, 0u);
            __threadfence();
            g_gen = lg + 1;
        } else {
            while (g_gen != lg + 1) { }
        }
        lg = lg + 1;
        __threadfence();       // acquire
    }
    __syncthreads();
}

// ---------------- persistent-kernel GEMM phase ----------------
// Computes C[m0:m0+32, n0:n0+NW] = epi( (A + c*Kadd)[m0:m0+32, :] @ Ws^T + bias )
// Ws is the SMEM-resident weight slice in [k][n] layout (stride NW).
// 256 threads = 4 K-groups x (8x8 thread grid), each thread 4xTN register tile.
// EPI: 0 = bias, 1 = bias+tanh, 2 = RK4 combine (v is k4; writes zout only)
template<int KDIM, int NW, int EPI>
__device__ __forceinline__ void phase(
    const float* __restrict__ Aop, const float* __restrict__ Kadd, float c,
    const float* __restrict__ Ws, const float* __restrict__ bias,
    float* __restrict__ Cout, int m0, int n0, int Nfull,
    float* __restrict__ As, float* __restrict__ red,
    const float* __restrict__ zn, const float* __restrict__ Kk1,
    const float* __restrict__ Kk2, const float* __restrict__ Kk3,
    float* __restrict__ zout, float hh)
{
    const int tid = threadIdx.x;

    // ---- stage A tile (32 rows x KDIM) into As[k][m] (stride 32), L2-only loads
    {
        const int m  = tid & 31;
        const int kq = tid >> 5;   // 0..7
        const float* arow = Aop + (size_t)(m0 + m) * KDIM;
        const float* krow = Kadd ? Kadd + (size_t)(m0 + m) * KDIM : nullptr;
#pragma unroll
        for (int it = 0; it < KDIM / 32; ++it) {
            const int k = (it * 8 + kq) * 4;
            float4 av = __ldcg((const float4*)(arow + k));
            if (Kadd) {
                const float4 kv = __ldcg((const float4*)(krow + k));
                av.x += c * kv.x; av.y += c * kv.y;
                av.z += c * kv.z; av.w += c * kv.w;
            }
            As[(k + 0) * 32 + m] = av.x;
            As[(k + 1) * 32 + m] = av.y;
            As[(k + 2) * 32 + m] = av.z;
            As[(k + 3) * 32 + m] = av.w;
        }
    }
    __syncthreads();

    constexpr int TN = NW / 8;
    constexpr int KG = KDIM / 4;
    const int g  = tid >> 6;      // K-group 0..3
    const int t  = tid & 63;
    const int tm = t >> 3;        // 0..7
    const int tn = t & 7;         // 0..7

    float acc[4][TN];
#pragma unroll
    for (int i = 0; i < 4; i++)
#pragma unroll
        for (int j = 0; j < TN; j++) acc[i][j] = 0.f;

    const float* Ag = As + g * KG * 32 + tm * 4;
    const float* Wg = Ws + g * KG * NW + tn * TN;
#pragma unroll 4
    for (int k = 0; k < KG; ++k) {
        const float4 a4 = *(const float4*)(Ag + k * 32);
        float av[4] = {a4.x, a4.y, a4.z, a4.w};
        float bv[TN];
        if constexpr (TN == 4) {
            const float4 b4 = *(const float4*)(Wg + k * NW);
            bv[0] = b4.x; bv[1] = b4.y; bv[2] = b4.z; bv[3] = b4.w;
        } else {
            const float2 b2 = *(const float2*)(Wg + k * NW);
            bv[0] = b2.x; bv[1] = b2.y;
        }
#pragma unroll
        for (int i = 0; i < 4; ++i)
#pragma unroll
            for (int j = 0; j < TN; ++j)
                acc[i][j] = fmaf(av[i], bv[j], acc[i][j]);
    }

    // ---- cross-K-group reduction via smem
#pragma unroll
    for (int i = 0; i < 4; ++i)
#pragma unroll
        for (int j = 0; j < TN; ++j)
            red[(g * 32 + tm * 4 + i) * NW + tn * TN + j] = acc[i][j];
    __syncthreads();

    for (int e = tid; e < 32 * NW; e += 256) {
        const int m = e / NW, n = e % NW;
        float v = red[m * NW + n] + red[(32 + m) * NW + n] +
                  red[(64 + m) * NW + n] + red[(96 + m) * NW + n];
        v += bias[n0 + n];
        if (EPI == 1) v = tanhf(v);
        if (EPI == 2) {
            const size_t idx = (size_t)(m0 + m) * Nfull + n0 + n;
            zout[idx] = __ldcg(zn + idx) +
                        hh * (1.f / 6.f) *
                        (__ldcg(Kk1 + idx) + 2.f * __ldcg(Kk2 + idx) +
                         2.f * __ldcg(Kk3 + idx) + v);
        } else {
            Cout[(size_t)(m0 + m) * Nfull + n0 + n] = v;
        }
    }
}

// ---------------- persistent ODE kernel: 199 RK4 steps in one launch ----------------
__global__ void __launch_bounds__(256, 1) ode_kernel(
    const float* __restrict__ t,
    const float* __restrict__ fw0, const float* __restrict__ fb0,
    const float* __restrict__ fw1, const float* __restrict__ fb1,
    const float* __restrict__ fw2, const float* __restrict__ fb2,
    float* __restrict__ zbuf, float* __restrict__ h1buf,
    float* __restrict__ h2buf, float* __restrict__ kst)
{
    extern __shared__ float smem[];
    float* W0s = smem;                 // 256k x 32n  =  8192 f
    float* W1s = W0s + 256 * 32;       // 512k x 32n  = 16384 f
    float* W2s = W1s + 512 * 32;       // 512k x 16n  =  8192 f
    float* As  = W2s + 512 * 16;       // 512k x 32m  = 16384 f
    float* red = As  + 512 * 32;       // 4 x 32 x 32 =  4096 f
                                       // total 53248 f = 208 KB

    const int tid = threadIdx.x;
    const int b   = blockIdx.x;
    const int m0  = (b >> 4) * 32;     // 8 M-tiles
    const int nT  = b & 15;            // 16 N-tiles
    const int n0w = nT * 32;           // phases A,B (N=512)
    const int n0c = nT * 16;           // phase C   (N=256)

    // ---- stage weight slices into SMEM ([k][n] layout), once per launch
    for (int e = tid; e < 32 * 256; e += 256) {
        const int n = e >> 8, k = e & 255;
        W0s[k * 32 + n] = fw0[(size_t)(n0w + n) * 256 + k];
    }
    for (int e = tid; e < 32 * 512; e += 256) {
        const int n = e >> 9, k = e & 511;
        W1s[k * 32 + n] = fw1[(size_t)(n0w + n) * 512 + k];
    }
    for (int e = tid; e < 16 * 512; e += 256) {
        const int n = e >> 9, k = e & 511;
        W2s[k * 16 + n] = fw2[(size_t)(n0c + n) * 512 + k];
    }
    __syncthreads();

    unsigned lg = 0;
    if (tid == 0) lg = g_gen;   // resume from whatever generation the last replay left

    float* K1 = kst;
    float* K2 = kst + BSZ * LATD;
    float* K3 = kst + 2 * BSZ * LATD;

    for (int n = 0; n < TSTEPS - 1; n++) {
        const float hh = t[n + 1] - t[n];
        const float* zn = zbuf + (size_t)n * (BSZ * LATD);
        float* znx      = zbuf + (size_t)(n + 1) * (BSZ * LATD);

        // stage 1: k1 = rhs(z)
        phase<256, 32, 1>(zn, nullptr, 0.f, W0s, fb0, h1buf, m0, n0w, 512, As, red, 0, 0, 0, 0, 0, 0.f);
        gsync(lg);
        phase<512, 32, 1>(h1buf, nullptr, 0.f, W1s, fb1, h2buf, m0, n0w, 512, As, red, 0, 0, 0, 0, 0, 0.f);
        gsync(lg);
        phase<512, 16, 0>(h2buf, nullptr, 0.f, W2s, fb2, K1, m0, n0c, 256, As, red, 0, 0, 0, 0, 0, 0.f);
        gsync(lg);
        // stage 2: k2 = rhs(z + 0.5h k1)
        phase<256, 32, 1>(zn, K1, 0.5f * hh, W0s, fb0, h1buf, m0, n0w, 512, As, red, 0, 0, 0, 0, 0, 0.f);
        gsync(lg);
        phase<512, 32, 1>(h1buf, nullptr, 0.f, W1s, fb1, h2buf, m0, n0w, 512, As, red, 0, 0, 0, 0, 0, 0.f);
        gsync(lg);
        phase<512, 16, 0>(h2buf, nullptr, 0.f, W2s, fb2, K2, m0, n0c, 256, As, red, 0, 0, 0, 0, 0, 0.f);
        gsync(lg);
        // stage 3: k3 = rhs(z + 0.5h k2)
        phase<256, 32, 1>(zn, K2, 0.5f * hh, W0s, fb0, h1buf, m0, n0w, 512, As, red, 0, 0, 0, 0, 0, 0.f);
        gsync(lg);
        phase<512, 32, 1>(h1buf, nullptr, 0.f, W1s, fb1, h2buf, m0, n0w, 512, As, red, 0, 0, 0, 0, 0, 0.f);
        gsync(lg);
        phase<512, 16, 0>(h2buf, nullptr, 0.f, W2s, fb2, K3, m0, n0c, 256, As, red, 0, 0, 0, 0, 0, 0.f);
        gsync(lg);
        // stage 4: k4 = rhs(z + h k3); fused z_{n+1} = z + h/6 (k1+2k2+2k3+k4)
        phase<256, 32, 1>(zn, K3, hh, W0s, fb0, h1buf, m0, n0w, 512, As, red, 0, 0, 0, 0, 0, 0.f);
        gsync(lg);
        phase<512, 32, 1>(h1buf, nullptr, 0.f, W1s, fb1, h2buf, m0, n0w, 512, As, red, 0, 0, 0, 0, 0, 0.f);
        gsync(lg);
        phase<512, 16, 2>(h2buf, nullptr, 0.f, W2s, fb2, nullptr, m0, n0c, 256, As, red,
                          zn, K1, K2, K3, znx, hh);
        gsync(lg);
    }
}

// ---------------- generic NT GEMM (encoder + decoder launches) ----------------
// EPI: 0 = bias, 1 = bias+tanh, 3 = bias + transposed store into (B,SIG,T)
template<int BM, int BN, int BK, int TM, int TN, int EPI>
__launch_bounds__(256)
__global__ void gemm_nt(const float* __restrict__ A,
                        const float* __restrict__ W,
                        const float* __restrict__ bias,
                        float* __restrict__ C,
                        int M, int N, int K)
{
    static_assert((BM / TM) * (BN / TN) == 256, "256 threads");
    static_assert(BM * BK / 4 == 256 && BN * BK / 4 == 256, "one float4/thread/tile");
    constexpr int PAD = (TM == 2) ? 2 : 4;
    __shared__ float As[BK][BM + PAD];
    __shared__ float Bs[BK][BN + PAD];

    const int tid = threadIdx.x;
    const int tx  = tid % (BN / TN);
    const int ty  = tid / (BN / TN);
    const int m0  = blockIdx.y * BM;
    const int n0  = blockIdx.x * BN;

    const int ar = tid / (BK / 4);
    const int ak = (tid % (BK / 4)) * 4;

    float acc[TM][TN];
#pragma unroll
    for (int i = 0; i < TM; i++)
#pragma unroll
        for (int j = 0; j < TN; j++) acc[i][j] = 0.f;

    const float* Aptr = A + (size_t)(m0 + ar) * K + ak;
    const float* Wptr = W + (size_t)(n0 + ar) * K + ak;

    for (int k0 = 0; k0 < K; k0 += BK) {
        const float4 av = *(const float4*)(Aptr + k0);
        const float4 bv = *(const float4*)(Wptr + k0);
        As[ak + 0][ar] = av.x; As[ak + 1][ar] = av.y;
        As[ak + 2][ar] = av.z; As[ak + 3][ar] = av.w;
        Bs[ak + 0][ar] = bv.x; Bs[ak + 1][ar] = bv.y;
        Bs[ak + 2][ar] = bv.z; Bs[ak + 3][ar] = bv.w;
        __syncthreads();
#pragma unroll
        for (int k = 0; k < BK; k++) {
            float a[TM], bb[TN];
#pragma unroll
            for (int i = 0; i < TM; i++) a[i] = As[k][ty * TM + i];
#pragma unroll
            for (int j = 0; j < TN; j++) bb[j] = Bs[k][tx * TN + j];
#pragma unroll
            for (int i = 0; i < TM; i++)
#pragma unroll
                for (int j = 0; j < TN; j++) acc[i][j] += a[i] * bb[j];
        }
        __syncthreads();
    }

#pragma unroll
    for (int i = 0; i < TM; i++) {
        const int m = m0 + ty * TM + i;
#pragma unroll
        for (int j = 0; j < TN; j++) {
            const int n = n0 + tx * TN + j;
            float v = acc[i][j] + bias[n];
            if (EPI == 1) v = tanhf(v);
            if (EPI == 0 || EPI == 1) {
                C[(size_t)m * N + n] = v;
            } else { // EPI == 3: m = t*BSZ + b, n = s -> out[b, s, t]
                const int tt = m >> 8;
                const int bb2 = m & 255;
                C[(size_t)bb2 * (SIG * TSTEPS) + (size_t)n * TSTEPS + tt] = v;
            }
        }
    }
}

// ------------- fused weight concat for encoder -------------
__global__ void wcat_kernel(const float* __restrict__ ew, const float* __restrict__ eb,
                            const float* __restrict__ rw, const float* __restrict__ rb,
                            float* __restrict__ Wc, float* __restrict__ bc,
                            int IN, int mode)
{
    const int o  = blockIdx.x;
    const int Kc = (mode == 0) ? IN * 4 : IN * 3;
    for (int cidx = threadIdx.x; cidx < Kc; cidx += blockDim.x) {
        float v;
        if (mode == 0) {
            if (cidx < IN * 3) v = ew[o * IN * 3 + cidx];
            else               v = rw[o * IN + (cidx - IN * 3)];
        } else {
            if (cidx < IN)          v = ew[o * IN * 3 + cidx * 3 + 1];
            else if (cidx < 2 * IN) v = ew[o * IN * 3 + (cidx - IN) * 3 + 2];
            else                    v = rw[o * IN + (cidx - 2 * IN)];
        }
        Wc[o * Kc + cidx] = v;
    }
    if (threadIdx.x == 0) bc[o] = eb[o] + rb[o];
}

// ------------- im2col gathers (receptive field of l=0 only) -------------
__global__ void gather0(const float* __restrict__ y, float* __restrict__ A0)
{
    const int row = blockIdx.x;
    const int l = row >> 8, b = row & 255;
    for (int cidx = threadIdx.x; cidx < 256; cidx += blockDim.x) {
        float v;
        if (cidx < 192) {
            const int i = cidx / 3, k = cidx % 3, p = l + k - 1;
            v = (p >= 0) ? y[(size_t)b * (SIG * 1024) + i * 1024 + p] : 0.f;
        } else {
            const int i = cidx - 192;
            v = y[(size_t)b * (SIG * 1024) + i * 1024 + l];
        }
        A0[(size_t)row * 256 + cidx] = v;
    }
}

__global__ void gather1(const float* __restrict__ x0, float* __restrict__ A1)
{
    const int row = blockIdx.x;
    const int l = row >> 8, b = row & 255;
    for (int cidx = threadIdx.x; cidx < 1024; cidx += blockDim.x) {
        float v;
        if (cidx < 768) {
            const int i = cidx / 3, k = cidx % 3, p = l + k - 1;
            v = (p >= 0) ? x0[(size_t)(p * 256 + b) * 256 + i] : 0.f;
        } else {
            const int i = cidx - 768;
            v = x0[(size_t)(l * 256 + b) * 256 + i];
        }
        A1[(size_t)row * 1024 + cidx] = v;
    }
}

__global__ void gather2(const float* __restrict__ x1, float* __restrict__ A2)
{
    const int b = blockIdx.x;
    for (int cidx = threadIdx.x; cidx < 768; cidx += blockDim.x) {
        float v;
        if (cidx < 256)      v = x1[(size_t)b * 256 + cidx];
        else if (cidx < 512) v = x1[(size_t)(256 + b) * 256 + (cidx - 256)];
        else                 v = x1[(size_t)b * 256 + (cidx - 512)];
        A2[(size_t)b * 768 + cidx] = v;
    }
}

// ---------------- host-side helpers ----------------
template<int EPI>
static void rungemmA(const float* A, const float* W, const float* bias,
                     float* C, int M, int N, int K)
{
    dim3 g(N / 32, M / 32);
    gemm_nt<32, 32, 32, 2, 2, EPI><<<g, 256>>>(A, W, bias, C, M, N, K);
}

template<int EPI>
static void rungemmB(const float* A, const float* W, const float* bias,
                     float* C, int M, int N, int K)
{
    dim3 g(N / 64, M / 64);
    gemm_nt<64, 64, 16, 4, 4, EPI><<<g, 256>>>(A, W, bias, C, M, N, K);
}

extern "C" void kernel_launch(void* const* d_in, const int* in_sizes, int n_in,
                              void* d_out, int out_size)
{
    const float* y   = (const float*)d_in[0];
    const float* t   = (const float*)d_in[1];
    const float* ew0 = (const float*)d_in[2];
    const float* eb0 = (const float*)d_in[3];
    const float* rw0 = (const float*)d_in[4];
    const float* rb0 = (const float*)d_in[5];
    const float* ew1 = (const float*)d_in[6];
    const float* eb1 = (const float*)d_in[7];
    const float* rw1 = (const float*)d_in[8];
    const float* rb1 = (const float*)d_in[9];
    const float* ew2 = (const float*)d_in[10];
    const float* eb2 = (const float*)d_in[11];
    const float* rw2 = (const float*)d_in[12];
    const float* rb2 = (const float*)d_in[13];
    const float* fw0 = (const float*)d_in[14];
    const float* fb0 = (const float*)d_in[15];
    const float* fw1 = (const float*)d_in[16];
    const float* fb1 = (const float*)d_in[17];
    const float* fw2 = (const float*)d_in[18];
    const float* fb2 = (const float*)d_in[19];
    const float* dw0 = (const float*)d_in[20];
    const float* db0 = (const float*)d_in[21];
    const float* dw1 = (const float*)d_in[22];
    const float* db1 = (const float*)d_in[23];
    const float* dw2 = (const float*)d_in[24];
    const float* db2 = (const float*)d_in[25];
    float* out = (float*)d_out;

    float *zbuf, *h1, *h2, *kst, *x0, *x1, *A0, *A1, *A2;
    float *Wc0, *Wc1, *Wc2, *bc0, *bc1, *bc2, *hd1, *hd2;
    cudaGetSymbolAddress((void**)&zbuf, g_z);
    cudaGetSymbolAddress((void**)&h1,  g_h1);
    cudaGetSymbolAddress((void**)&h2,  g_h2);
    cudaGetSymbolAddress((void**)&kst, g_kst);
    cudaGetSymbolAddress((void**)&x0,  g_x0);
    cudaGetSymbolAddress((void**)&x1,  g_x1);
    cudaGetSymbolAddress((void**)&A0,  g_A0);
    cudaGetSymbolAddress((void**)&A1,  g_A1);
    cudaGetSymbolAddress((void**)&A2,  g_A2);
    cudaGetSymbolAddress((void**)&Wc0, g_Wc0);
    cudaGetSymbolAddress((void**)&Wc1, g_Wc1);
    cudaGetSymbolAddress((void**)&Wc2, g_Wc2);
    cudaGetSymbolAddress((void**)&bc0, g_bc0);
    cudaGetSymbolAddress((void**)&bc1, g_bc1);
    cudaGetSymbolAddress((void**)&bc2, g_bc2);
    cudaGetSymbolAddress((void**)&hd1, g_hd1);
    cudaGetSymbolAddress((void**)&hd2, g_hd2);

    // ---------- encoder ----------
    wcat_kernel<<<ENCH, 256>>>(ew0, eb0, rw0, rb0, Wc0, bc0, SIG, 0);
    wcat_kernel<<<ENCH, 256>>>(ew1, eb1, rw1, rb1, Wc1, bc1, ENCH, 0);
    wcat_kernel<<<LATD, 256>>>(ew2, eb2, rw2, rb2, Wc2, bc2, ENCH, 1);

    gather0<<<3 * BSZ, 256>>>(y, A0);
    rungemmA<1>(A0, Wc0, bc0, x0, 3 * BSZ, ENCH, 256);
    gather1<<<2 * BSZ, 256>>>(x0, A1);
    rungemmA<1>(A1, Wc1, bc1, x1, 2 * BSZ, ENCH, 1024);
    gather2<<<BSZ, 256>>>(x1, A2);
    rungemmA<0>(A2, Wc2, bc2, zbuf /* z0 */, BSZ, LATD, 768);

    // ---------- RK4 ODE: one persistent kernel ----------
    const int smem_bytes = (256 * 32 + 512 * 32 + 512 * 16 + 512 * 32 + 4096) * 4;
    cudaFuncSetAttribute(ode_kernel, cudaFuncAttributeMaxDynamicSharedMemorySize,
                         smem_bytes);
    ode_kernel<<<NBLK, 256, smem_bytes>>>(t, fw0, fb0, fw1, fb1, fw2, fb2,
                                          zbuf, h1, h2, kst);

    // ---------- decoder over all 200 states ----------
    rungemmB<1>(zbuf, dw0, db0, hd1, TSTEPS * BSZ, DECH, LATD);
    rungemmB<1>(hd1,  dw1, db1, hd2, TSTEPS * BSZ, DECH, DECH);
    rungemmB<3>(hd2,  dw2, db2, out, TSTEPS * BSZ, SIG,  DECH);
}

// round 3
// speedup vs baseline: 1.0061x; 1.0061x over previous
#include <cuda_runtime.h>
#include <cuda_bf16.h>
#include <math.h>

// Problem dims
#define BSZ   256
#define SIG   64
#define LATD  256
#define ENCH  256
#define DECH  512
#define RHSH  512
#define TSTEPS 200

#define NBLK  128   // persistent ODE grid (<= 148 SMs, 1 block/SM via smem)

// ---------------- scratch (device globals; no allocation) ----------------
__device__ float g_z[TSTEPS * BSZ * LATD];        // pred_z, 52.4 MB
__device__ float g_h1[BSZ * RHSH];
__device__ float g_h2[BSZ * RHSH];
__device__ float g_kst[3 * BSZ * LATD];           // k1,k2,k3
__device__ float g_x0[3 * BSZ * ENCH];
__device__ float g_x1[2 * BSZ * ENCH];
__device__ float g_A0[3 * BSZ * 256];
__device__ float g_A1[2 * BSZ * 1024];
__device__ float g_A2[BSZ * 768];
__device__ float g_Wc0[ENCH * 256];
__device__ float g_Wc1[ENCH * 1024];
__device__ float g_Wc2[LATD * 768];
__device__ float g_bc0[ENCH];
__device__ float g_bc1[ENCH];
__device__ float g_bc2[LATD];
__device__ float g_hd1[(size_t)TSTEPS * BSZ * DECH];
__device__ float g_hd2[(size_t)TSTEPS * BSZ * DECH];

// ---------------- software grid barrier ----------------
__device__ unsigned g_arr = 0;
__device__ volatile unsigned g_gen = 0;

__device__ __forceinline__ void gsync(unsigned& lg)
{
    __threadfence();           // release: make this thread's gmem writes visible
    __syncthreads();
    if (threadIdx.x == 0) {
        const unsigned ticket = atomicAdd(&g_arr, 1u);
        if (ticket == gridDim.x - 1) {
            atomicExch(&g_arr, 0u);
            __threadfence();
            g_gen = lg + 1;
        } else {
            while (g_gen != lg + 1) { }
        }
        lg = lg + 1;
        __threadfence();       // acquire
    }
    __syncthreads();
}

// ---------------- persistent-kernel GEMM phase ----------------
// Computes C[m0:m0+32, n0:n0+NW] = epi( (A + c*Kadd)[m0:m0+32, :] @ Ws^T + bias )
// Ws is the SMEM-resident weight slice in [k][n] layout (stride NW).
// 256 threads = 4 K-groups x (8x8 thread grid), each thread 4xTN register tile.
// EPI: 0 = bias, 1 = bias+tanh, 2 = RK4 combine (v is k4; writes zout only)
template<int KDIM, int NW, int EPI>
__device__ __forceinline__ void phase(
    const float* __restrict__ Aop, const float* __restrict__ Kadd, float c,
    const float* __restrict__ Ws, const float* __restrict__ bias,
    float* __restrict__ Cout, int m0, int n0, int Nfull,
    float* __restrict__ As, float* __restrict__ red,
    const float* __restrict__ zn, const float* __restrict__ Kk1,
    const float* __restrict__ Kk2, const float* __restrict__ Kk3,
    float* __restrict__ zout, float hh)
{
    const int tid = threadIdx.x;

    // ---- stage A tile (32 rows x KDIM) into As[k][m] (stride 32), L2-only loads
    {
        const int m  = tid & 31;
        const int kq = tid >> 5;   // 0..7
        const float* arow = Aop + (size_t)(m0 + m) * KDIM;
        const float* krow = Kadd ? Kadd + (size_t)(m0 + m) * KDIM : nullptr;
#pragma unroll
        for (int it = 0; it < KDIM / 32; ++it) {
            const int k = (it * 8 + kq) * 4;
            float4 av = __ldcg((const float4*)(arow + k));
            if (Kadd) {
                const float4 kv = __ldcg((const float4*)(krow + k));
                av.x += c * kv.x; av.y += c * kv.y;
                av.z += c * kv.z; av.w += c * kv.w;
            }
            As[(k + 0) * 32 + m] = av.x;
            As[(k + 1) * 32 + m] = av.y;
            As[(k + 2) * 32 + m] = av.z;
            As[(k + 3) * 32 + m] = av.w;
        }
    }
    __syncthreads();

    constexpr int TN = NW / 8;
    constexpr int KG = KDIM / 4;
    const int g  = tid >> 6;      // K-group 0..3
    const int t  = tid & 63;
    const int tm = t >> 3;        // 0..7
    const int tn = t & 7;         // 0..7

    float acc[4][TN];
#pragma unroll
    for (int i = 0; i < 4; i++)
#pragma unroll
        for (int j = 0; j < TN; j++) acc[i][j] = 0.f;

    const float* Ag = As + g * KG * 32 + tm * 4;
    const float* Wg = Ws + g * KG * NW + tn * TN;
#pragma unroll 4
    for (int k = 0; k < KG; ++k) {
        const float4 a4 = *(const float4*)(Ag + k * 32);
        float av[4] = {a4.x, a4.y, a4.z, a4.w};
        float bv[TN];
        if constexpr (TN == 4) {
            const float4 b4 = *(const float4*)(Wg + k * NW);
            bv[0] = b4.x; bv[1] = b4.y; bv[2] = b4.z; bv[3] = b4.w;
        } else {
            const float2 b2 = *(const float2*)(Wg + k * NW);
            bv[0] = b2.x; bv[1] = b2.y;
        }
#pragma unroll
        for (int i = 0; i < 4; ++i)
#pragma unroll
            for (int j = 0; j < TN; ++j)
                acc[i][j] = fmaf(av[i], bv[j], acc[i][j]);
    }

    // ---- cross-K-group reduction via smem
#pragma unroll
    for (int i = 0; i < 4; ++i)
#pragma unroll
        for (int j = 0; j < TN; ++j)
            red[(g * 32 + tm * 4 + i) * NW + tn * TN + j] = acc[i][j];
    __syncthreads();

    for (int e = tid; e < 32 * NW; e += 256) {
        const int m = e / NW, n = e % NW;
        float v = red[m * NW + n] + red[(32 + m) * NW + n] +
                  red[(64 + m) * NW + n] + red[(96 + m) * NW + n];
        v += bias[n0 + n];
        if (EPI == 1) v = tanhf(v);
        if (EPI == 2) {
            const size_t idx = (size_t)(m0 + m) * Nfull + n0 + n;
            zout[idx] = __ldcg(zn + idx) +
                        hh * (1.f / 6.f) *
                        (__ldcg(Kk1 + idx) + 2.f * __ldcg(Kk2 + idx) +
                         2.f * __ldcg(Kk3 + idx) + v);
        } else {
            Cout[(size_t)(m0 + m) * Nfull + n0 + n] = v;
        }
    }
}

// ---------------- persistent ODE kernel: 199 RK4 steps in one launch ----------------
__global__ void __launch_bounds__(256, 1) ode_kernel(
    const float* __restrict__ t,
    const float* __restrict__ fw0, const float* __restrict__ fb0,
    const float* __restrict__ fw1, const float* __restrict__ fb1,
    const float* __restrict__ fw2, const float* __restrict__ fb2,
    float* __restrict__ zbuf, float* __restrict__ h1buf,
    float* __restrict__ h2buf, float* __restrict__ kst)
{
    extern __shared__ float smem[];
    float* W0s = smem;                 // 256k x 32n  =  8192 f
    float* W1s = W0s + 256 * 32;       // 512k x 32n  = 16384 f
    float* W2s = W1s + 512 * 32;       // 512k x 16n  =  8192 f
    float* As  = W2s + 512 * 16;       // 512k x 32m  = 16384 f
    float* red = As  + 512 * 32;       // 4 x 32 x 32 =  4096 f
                                       // total 53248 f = 208 KB

    const int tid = threadIdx.x;
    const int b   = blockIdx.x;
    const int m0  = (b >> 4) * 32;     // 8 M-tiles
    const int nT  = b & 15;            // 16 N-tiles
    const int n0w = nT * 32;           // phases A,B (N=512)
    const int n0c = nT * 16;           // phase C   (N=256)

    // ---- stage weight slices into SMEM ([k][n] layout), once per launch
    for (int e = tid; e < 32 * 256; e += 256) {
        const int n = e >> 8, k = e & 255;
        W0s[k * 32 + n] = fw0[(size_t)(n0w + n) * 256 + k];
    }
    for (int e = tid; e < 32 * 512; e += 256) {
        const int n = e >> 9, k = e & 511;
        W1s[k * 32 + n] = fw1[(size_t)(n0w + n) * 512 + k];
    }
    for (int e = tid; e < 16 * 512; e += 256) {
        const int n = e >> 9, k = e & 511;
        W2s[k * 16 + n] = fw2[(size_t)(n0c + n) * 512 + k];
    }
    __syncthreads();

    unsigned lg = 0;
    if (tid == 0) lg = g_gen;   // resume from whatever generation the last replay left

    float* K1 = kst;
    float* K2 = kst + BSZ * LATD;
    float* K3 = kst + 2 * BSZ * LATD;

    for (int n = 0; n < TSTEPS - 1; n++) {
        const float hh = t[n + 1] - t[n];
        const float* zn = zbuf + (size_t)n * (BSZ * LATD);
        float* znx      = zbuf + (size_t)(n + 1) * (BSZ * LATD);

        // stage 1: k1 = rhs(z)
        phase<256, 32, 1>(zn, nullptr, 0.f, W0s, fb0, h1buf, m0, n0w, 512, As, red, 0, 0, 0, 0, 0, 0.f);
        gsync(lg);
        phase<512, 32, 1>(h1buf, nullptr, 0.f, W1s, fb1, h2buf, m0, n0w, 512, As, red, 0, 0, 0, 0, 0, 0.f);
        gsync(lg);
        phase<512, 16, 0>(h2buf, nullptr, 0.f, W2s, fb2, K1, m0, n0c, 256, As, red, 0, 0, 0, 0, 0, 0.f);
        gsync(lg);
        // stage 2: k2 = rhs(z + 0.5h k1)
        phase<256, 32, 1>(zn, K1, 0.5f * hh, W0s, fb0, h1buf, m0, n0w, 512, As, red, 0, 0, 0, 0, 0, 0.f);
        gsync(lg);
        phase<512, 32, 1>(h1buf, nullptr, 0.f, W1s, fb1, h2buf, m0, n0w, 512, As, red, 0, 0, 0, 0, 0, 0.f);
        gsync(lg);
        phase<512, 16, 0>(h2buf, nullptr, 0.f, W2s, fb2, K2, m0, n0c, 256, As, red, 0, 0, 0, 0, 0, 0.f);
        gsync(lg);
        // stage 3: k3 = rhs(z + 0.5h k2)
        phase<256, 32, 1>(zn, K2, 0.5f * hh, W0s, fb0, h1buf, m0, n0w, 512, As, red, 0, 0, 0, 0, 0, 0.f);
        gsync(lg);
        phase<512, 32, 1>(h1buf, nullptr, 0.f, W1s, fb1, h2buf, m0, n0w, 512, As, red, 0, 0, 0, 0, 0, 0.f);
        gsync(lg);
        phase<512, 16, 0>(h2buf, nullptr, 0.f, W2s, fb2, K3, m0, n0c, 256, As, red, 0, 0, 0, 0, 0, 0.f);
        gsync(lg);
        // stage 4: k4 = rhs(z + h k3); fused z_{n+1} = z + h/6 (k1+2k2+2k3+k4)
        phase<256, 32, 1>(zn, K3, hh, W0s, fb0, h1buf, m0, n0w, 512, As, red, 0, 0, 0, 0, 0, 0.f);
        gsync(lg);
        phase<512, 32, 1>(h1buf, nullptr, 0.f, W1s, fb1, h2buf, m0, n0w, 512, As, red, 0, 0, 0, 0, 0, 0.f);
        gsync(lg);
        phase<512, 16, 2>(h2buf, nullptr, 0.f, W2s, fb2, nullptr, m0, n0c, 256, As, red,
                          zn, K1, K2, K3, znx, hh);
        gsync(lg);
    }
}

// ---------------- generic NT GEMM (encoder + decoder launches) ----------------
// EPI: 0 = bias, 1 = bias+tanh, 3 = bias + transposed store into (B,SIG,T)
template<int BM, int BN, int BK, int TM, int TN, int EPI>
__launch_bounds__(256)
__global__ void gemm_nt(const float* __restrict__ A,
                        const float* __restrict__ W,
                        const float* __restrict__ bias,
                        float* __restrict__ C,
                        int M, int N, int K)
{
    static_assert((BM / TM) * (BN / TN) == 256, "256 threads");
    static_assert(BM * BK / 4 == 256 && BN * BK / 4 == 256, "one float4/thread/tile");
    constexpr int PAD = (TM == 2) ? 2 : 4;
    __shared__ float As[BK][BM + PAD];
    __shared__ float Bs[BK][BN + PAD];

    const int tid = threadIdx.x;
    const int tx  = tid % (BN / TN);
    const int ty  = tid / (BN / TN);
    const int m0  = blockIdx.y * BM;
    const int n0  = blockIdx.x * BN;

    const int ar = tid / (BK / 4);
    const int ak = (tid % (BK / 4)) * 4;

    float acc[TM][TN];
#pragma unroll
    for (int i = 0; i < TM; i++)
#pragma unroll
        for (int j = 0; j < TN; j++) acc[i][j] = 0.f;

    const float* Aptr = A + (size_t)(m0 + ar) * K + ak;
    const float* Wptr = W + (size_t)(n0 + ar) * K + ak;

    for (int k0 = 0; k0 < K; k0 += BK) {
        const float4 av = *(const float4*)(Aptr + k0);
        const float4 bv = *(const float4*)(Wptr + k0);
        As[ak + 0][ar] = av.x; As[ak + 1][ar] = av.y;
        As[ak + 2][ar] = av.z; As[ak + 3][ar] = av.w;
        Bs[ak + 0][ar] = bv.x; Bs[ak + 1][ar] = bv.y;
        Bs[ak + 2][ar] = bv.z; Bs[ak + 3][ar] = bv.w;
        __syncthreads();
#pragma unroll
        for (int k = 0; k < BK; k++) {
            float a[TM], bb[TN];
#pragma unroll
            for (int i = 0; i < TM; i++) a[i] = As[k][ty * TM + i];
#pragma unroll
            for (int j = 0; j < TN; j++) bb[j] = Bs[k][tx * TN + j];
#pragma unroll
            for (int i = 0; i < TM; i++)
#pragma unroll
                for (int j = 0; j < TN; j++) acc[i][j] += a[i] * bb[j];
        }
        __syncthreads();
    }

#pragma unroll
    for (int i = 0; i < TM; i++) {
        const int m = m0 + ty * TM + i;
#pragma unroll
        for (int j = 0; j < TN; j++) {
            const int n = n0 + tx * TN + j;
            float v = acc[i][j] + bias[n];
            if (EPI == 1) v = tanhf(v);
            if (EPI == 0 || EPI == 1) {
                C[(size_t)m * N + n] = v;
            } else { // EPI == 3: m = t*BSZ + b, n = s -> out[b, s, t]
                const int tt = m >> 8;
                const int bb2 = m & 255;
                C[(size_t)bb2 * (SIG * TSTEPS) + (size_t)n * TSTEPS + tt] = v;
            }
        }
    }
}

// ------------- fused weight concat for encoder -------------
__global__ void wcat_kernel(const float* __restrict__ ew, const float* __restrict__ eb,
                            const float* __restrict__ rw, const float* __restrict__ rb,
                            float* __restrict__ Wc, float* __restrict__ bc,
                            int IN, int mode)
{
    const int o  = blockIdx.x;
    const int Kc = (mode == 0) ? IN * 4 : IN * 3;
    for (int cidx = threadIdx.x; cidx < Kc; cidx += blockDim.x) {
        float v;
        if (mode == 0) {
            if (cidx < IN * 3) v = ew[o * IN * 3 + cidx];
            else               v = rw[o * IN + (cidx - IN * 3)];
        } else {
            if (cidx < IN)          v = ew[o * IN * 3 + cidx * 3 + 1];
            else if (cidx < 2 * IN) v = ew[o * IN * 3 + (cidx - IN) * 3 + 2];
            else                    v = rw[o * IN + (cidx - 2 * IN)];
        }
        Wc[o * Kc + cidx] = v;
    }
    if (threadIdx.x == 0) bc[o] = eb[o] + rb[o];
}

// ------------- im2col gathers (receptive field of l=0 only) -------------
__global__ void gather0(const float* __restrict__ y, float* __restrict__ A0)
{
    const int row = blockIdx.x;
    const int l = row >> 8, b = row & 255;
    for (int cidx = threadIdx.x; cidx < 256; cidx += blockDim.x) {
        float v;
        if (cidx < 192) {
            const int i = cidx / 3, k = cidx % 3, p = l + k - 1;
            v = (p >= 0) ? y[(size_t)b * (SIG * 1024) + i * 1024 + p] : 0.f;
        } else {
            const int i = cidx - 192;
            v = y[(size_t)b * (SIG * 1024) + i * 1024 + l];
        }
        A0[(size_t)row * 256 + cidx] = v;
    }
}

__global__ void gather1(const float* __restrict__ x0, float* __restrict__ A1)
{
    const int row = blockIdx.x;
    const int l = row >> 8, b = row & 255;
    for (int cidx = threadIdx.x; cidx < 1024; cidx += blockDim.x) {
        float v;
        if (cidx < 768) {
            const int i = cidx / 3, k = cidx % 3, p = l + k - 1;
            v = (p >= 0) ? x0[(size_t)(p * 256 + b) * 256 + i] : 0.f;
        } else {
            const int i = cidx - 768;
            v = x0[(size_t)(l * 256 + b) * 256 + i];
        }
        A1[(size_t)row * 1024 + cidx] = v;
    }
}

__global__ void gather2(const float* __restrict__ x1, float* __restrict__ A2)
{
    const int b = blockIdx.x;
    for (int cidx = threadIdx.x; cidx < 768; cidx += blockDim.x) {
        float v;
        if (cidx < 256)      v = x1[(size_t)b * 256 + cidx];
        else if (cidx < 512) v = x1[(size_t)(256 + b) * 256 + (cidx - 256)];
        else                 v = x1[(size_t)b * 256 + (cidx - 512)];
        A2[(size_t)b * 768 + cidx] = v;
    }
}

// ---------------- host-side helpers ----------------
template<int EPI>
static void rungemmA(const float* A, const float* W, const float* bias,
                     float* C, int M, int N, int K)
{
    dim3 g(N / 32, M / 32);
    gemm_nt<32, 32, 32, 2, 2, EPI><<<g, 256>>>(A, W, bias, C, M, N, K);
}

template<int EPI>
static void rungemmB(const float* A, const float* W, const float* bias,
                     float* C, int M, int N, int K)
{
    dim3 g(N / 64, M / 64);
    gemm_nt<64, 64, 16, 4, 4, EPI><<<g, 256>>>(A, W, bias, C, M, N, K);
}

extern "C" void kernel_launch(void* const* d_in, const int* in_sizes, int n_in,
                              void* d_out, int out_size)
{
    const float* y   = (const float*)d_in[0];
    const float* t   = (const float*)d_in[1];
    const float* ew0 = (const float*)d_in[2];
    const float* eb0 = (const float*)d_in[3];
    const float* rw0 = (const float*)d_in[4];
    const float* rb0 = (const float*)d_in[5];
    const float* ew1 = (const float*)d_in[6];
    const float* eb1 = (const float*)d_in[7];
    const float* rw1 = (const float*)d_in[8];
    const float* rb1 = (const float*)d_in[9];
    const float* ew2 = (const float*)d_in[10];
    const float* eb2 = (const float*)d_in[11];
    const float* rw2 = (const float*)d_in[12];
    const float* rb2 = (const float*)d_in[13];
    const float* fw0 = (const float*)d_in[14];
    const float* fb0 = (const float*)d_in[15];
    const float* fw1 = (const float*)d_in[16];
    const float* fb1 = (const float*)d_in[17];
    const float* fw2 = (const float*)d_in[18];
    const float* fb2 = (const float*)d_in[19];
    const float* dw0 = (const float*)d_in[20];
    const float* db0 = (const float*)d_in[21];
    const float* dw1 = (const float*)d_in[22];
    const float* db1 = (const float*)d_in[23];
    const float* dw2 = (const float*)d_in[24];
    const float* db2 = (const float*)d_in[25];
    float* out = (float*)d_out;

    float *zbuf, *h1, *h2, *kst, *x0, *x1, *A0, *A1, *A2;
    float *Wc0, *Wc1, *Wc2, *bc0, *bc1, *bc2, *hd1, *hd2;
    cudaGetSymbolAddress((void**)&zbuf, g_z);
    cudaGetSymbolAddress((void**)&h1,  g_h1);
    cudaGetSymbolAddress((void**)&h2,  g_h2);
    cudaGetSymbolAddress((void**)&kst, g_kst);
    cudaGetSymbolAddress((void**)&x0,  g_x0);
    cudaGetSymbolAddress((void**)&x1,  g_x1);
    cudaGetSymbolAddress((void**)&A0,  g_A0);
    cudaGetSymbolAddress((void**)&A1,  g_A1);
    cudaGetSymbolAddress((void**)&A2,  g_A2);
    cudaGetSymbolAddress((void**)&Wc0, g_Wc0);
    cudaGetSymbolAddress((void**)&Wc1, g_Wc1);
    cudaGetSymbolAddress((void**)&Wc2, g_Wc2);
    cudaGetSymbolAddress((void**)&bc0, g_bc0);
    cudaGetSymbolAddress((void**)&bc1, g_bc1);
    cudaGetSymbolAddress((void**)&bc2, g_bc2);
    cudaGetSymbolAddress((void**)&hd1, g_hd1);
    cudaGetSymbolAddress((void**)&hd2, g_hd2);

    // ---------- encoder ----------
    wcat_kernel<<<ENCH, 256>>>(ew0, eb0, rw0, rb0, Wc0, bc0, SIG, 0);
    wcat_kernel<<<ENCH, 256>>>(ew1, eb1, rw1, rb1, Wc1, bc1, ENCH, 0);
    wcat_kernel<<<LATD, 256>>>(ew2, eb2, rw2, rb2, Wc2, bc2, ENCH, 1);

    gather0<<<3 * BSZ, 256>>>(y, A0);
    rungemmA<1>(A0, Wc0, bc0, x0, 3 * BSZ, ENCH, 256);
    gather1<<<2 * BSZ, 256>>>(x0, A1);
    rungemmA<1>(A1, Wc1, bc1, x1, 2 * BSZ, ENCH, 1024);
    gather2<<<BSZ, 256>>>(x1, A2);
    rungemmA<0>(A2, Wc2, bc2, zbuf /* z0 */, BSZ, LATD, 768);

    // ---------- RK4 ODE: one persistent kernel ----------
    const int smem_bytes = (256 * 32 + 512 * 32 + 512 * 16 + 512 * 32 + 4096) * 4;
    cudaFuncSetAttribute(ode_kernel, cudaFuncAttributeMaxDynamicSharedMemorySize,
                         smem_bytes);
    ode_kernel<<<NBLK, 256, smem_bytes>>>(t, fw0, fb0, fw1, fb1, fw2, fb2,
                                          zbuf, h1, h2, kst);

    // ---------- decoder over all 200 states ----------
    rungemmB<1>(zbuf, dw0, db0, hd1, TSTEPS * BSZ, DECH, LATD);
    rungemmB<1>(hd1,  dw1, db1, hd2, TSTEPS * BSZ, DECH, DECH);
    rungemmB<3>(hd2,  dw2, db2, out, TSTEPS * BSZ, SIG,  DECH);
}

// round 4
// speedup vs baseline: 1.1516x; 1.1446x over previous
#include <cuda_runtime.h>
#include <cuda_bf16.h>
#include <math.h>

// Problem dims
#define BSZ   256
#define SIG   64
#define LATD  256
#define ENCH  256
#define DECH  512
#define RHSH  512
#define TSTEPS 200

#define NBLK   128   // persistent ODE grid: 8 M-groups x 16 N-blocks
#define GRPSZ  16    // blocks per independent M-group
#define NGRP   8

// ---------------- scratch (device globals; no allocation) ----------------
__device__ float g_z[TSTEPS * BSZ * LATD];        // pred_z
__device__ float g_h1[BSZ * RHSH];
__device__ float g_h2[BSZ * RHSH];
__device__ float g_kst[3 * BSZ * LATD];           // k1,k2,k3
__device__ float g_x0[3 * BSZ * ENCH];            // enc layer0 out, rows l*256+b
__device__ float g_x1[2 * BSZ * ENCH];            // enc layer1 out
__device__ float g_hd1[(size_t)TSTEPS * BSZ * DECH];
__device__ float g_hd2[(size_t)TSTEPS * BSZ * DECH];

// per-group barrier state (128B padding -> one L2 line per group)
__device__ unsigned g_arr[NGRP * 32];
__device__ unsigned g_gen[NGRP * 32];

// ---------------- f32x2 packed-FMA helpers ----------------
__device__ __forceinline__ void fma2(unsigned long long& d,
                                     unsigned long long a,
                                     unsigned long long b)
{
    asm("fma.rn.f32x2 %0, %1, %2, %0;" : "+l"(d) : "l"(a), "l"(b));
}
__device__ __forceinline__ unsigned long long pack2(float x)
{
    unsigned long long r;
    asm("mov.b64 %0, {%1, %1};" : "=l"(r) : "f"(x));
    return r;
}
__device__ __forceinline__ void unpack2(float& lo, float& hi, unsigned long long v)
{
    asm("mov.b64 {%0, %1}, %2;" : "=f"(lo), "=f"(hi) : "l"(v));
}

// ---------------- group barrier (16 blocks, release/acquire) ----------------
__device__ __forceinline__ void gsync(unsigned* arr, unsigned* gen, unsigned& lg)
{
    __syncthreads();
    if (threadIdx.x == 0) {
        unsigned ticket;
        asm volatile("atom.release.gpu.add.u32 %0, [%1], 1;"
                     : "=r"(ticket) : "l"(arr) : "memory");
        const unsigned target = lg + 1;
        if ((ticket & (GRPSZ - 1)) == GRPSZ - 1) {
            asm volatile("st.release.gpu.u32 [%0], %1;"
                         :: "l"(gen), "r"(target) : "memory");
        } else {
            unsigned g;
            do {
                asm volatile("ld.acquire.gpu.u32 %0, [%1];"
                             : "=r"(g) : "l"(gen) : "memory");
            } while ((int)(g - target) < 0);
        }
        lg = target;
    }
    __syncthreads();
}

// ---------------- persistent-kernel GEMM phase ----------------
// C[m0:m0+32, n0:n0+NW] = epi( (A + c*Kadd)[m0:m0+32, :] @ Ws^T + bias )
// Ws: SMEM-resident weight slice, [k][n] layout (stride NW).
// 256 threads = 4 K-groups x (8x8 thread grid); each thread 4xTN outputs,
// accumulated as 2xTN packed f32x2 (pairs along M).
// EPI: 0 = bias, 1 = bias+tanh, 2 = RK4 combine (v is k4; writes zout)
template<int KDIM, int NW, int EPI>
__device__ __forceinline__ void phase(
    const float* __restrict__ Aop, const float* __restrict__ Kadd, float c,
    const float* __restrict__ Ws, const float* __restrict__ bias,
    float* __restrict__ Cout, int m0, int n0, int Nfull,
    float* __restrict__ As, float* __restrict__ red,
    const float* __restrict__ zn, const float* __restrict__ Kk1,
    const float* __restrict__ Kk2, const float* __restrict__ Kk3,
    float* __restrict__ zout, float hh)
{
    const int tid = threadIdx.x;

    // ---- stage A tile (32 rows x KDIM) into As[k][m] (stride 32), L2-only
    {
        const int m  = tid & 31;
        const int kq = tid >> 5;   // 0..7
        const float* arow = Aop + (size_t)(m0 + m) * KDIM;
        const float* krow = Kadd ? Kadd + (size_t)(m0 + m) * KDIM : nullptr;
#pragma unroll
        for (int it = 0; it < KDIM / 32; ++it) {
            const int k = (it * 8 + kq) * 4;
            float4 av = __ldcg((const float4*)(arow + k));
            if (Kadd) {
                const float4 kv = __ldcg((const float4*)(krow + k));
                av.x += c * kv.x; av.y += c * kv.y;
                av.z += c * kv.z; av.w += c * kv.w;
            }
            As[(k + 0) * 32 + m] = av.x;
            As[(k + 1) * 32 + m] = av.y;
            As[(k + 2) * 32 + m] = av.z;
            As[(k + 3) * 32 + m] = av.w;
        }
    }
    __syncthreads();

    constexpr int TN = NW / 8;    // 4 or 2
    constexpr int KG = KDIM / 4;
    const int g  = tid >> 6;      // K-group 0..3
    const int t  = tid & 63;
    const int tm = t >> 3;        // 0..7
    const int tn = t & 7;         // 0..7

    unsigned long long acc2[2][TN];
#pragma unroll
    for (int i = 0; i < 2; i++)
#pragma unroll
        for (int j = 0; j < TN; j++) acc2[i][j] = 0ULL;

    const float* Ag = As + g * KG * 32 + tm * 4;
    const float* Wg = Ws + g * KG * NW + tn * TN;
#pragma unroll 4
    for (int k = 0; k < KG; ++k) {
        const ulonglong2 a2 = *(const ulonglong2*)(Ag + k * 32); // {m0,m1},{m2,m3}
        unsigned long long bb[TN];
        if constexpr (TN == 4) {
            const float4 b4 = *(const float4*)(Wg + k * NW);
            bb[0] = pack2(b4.x); bb[1] = pack2(b4.y);
            bb[2] = pack2(b4.z); bb[3] = pack2(b4.w);
        } else {
            const float2 b2 = *(const float2*)(Wg + k * NW);
            bb[0] = pack2(b2.x); bb[1] = pack2(b2.y);
        }
#pragma unroll
        for (int j = 0; j < TN; ++j) {
            fma2(acc2[0][j], a2.x, bb[j]);
            fma2(acc2[1][j], a2.y, bb[j]);
        }
    }

    // ---- cross-K-group reduction via smem (unpack pairs)
#pragma unroll
    for (int i = 0; i < 2; ++i)
#pragma unroll
        for (int j = 0; j < TN; ++j) {
            float lo, hi;
            unpack2(lo, hi, acc2[i][j]);
            red[(g * 32 + tm * 4 + 2 * i)     * NW + tn * TN + j] = lo;
            red[(g * 32 + tm * 4 + 2 * i + 1) * NW + tn * TN + j] = hi;
        }
    __syncthreads();

    for (int e = tid; e < 32 * NW; e += 256) {
        const int m = e / NW, n = e % NW;
        float v = red[m * NW + n] + red[(32 + m) * NW + n] +
                  red[(64 + m) * NW + n] + red[(96 + m) * NW + n];
        v += bias[n0 + n];
        if (EPI == 1) v = tanhf(v);
        if (EPI == 2) {
            const size_t idx = (size_t)(m0 + m) * Nfull + n0 + n;
            zout[idx] = __ldcg(zn + idx) +
                        hh * (1.f / 6.f) *
                        (__ldcg(Kk1 + idx) + 2.f * __ldcg(Kk2 + idx) +
                         2.f * __ldcg(Kk3 + idx) + v);
        } else {
            Cout[(size_t)(m0 + m) * Nfull + n0 + n] = v;
        }
    }
    __syncthreads();
}

// ---------------- persistent ODE kernel ----------------
__global__ void __launch_bounds__(256, 1) ode_kernel(
    const float* __restrict__ t,
    const float* __restrict__ fw0, const float* __restrict__ fb0,
    const float* __restrict__ fw1, const float* __restrict__ fb1,
    const float* __restrict__ fw2, const float* __restrict__ fb2,
    float* __restrict__ zbuf, float* __restrict__ h1buf,
    float* __restrict__ h2buf, float* __restrict__ kst)
{
    extern __shared__ float smem[];
    float* W0s = smem;                 // 256k x 32n  =  8192 f
    float* W1s = W0s + 256 * 32;       // 512k x 32n  = 16384 f
    float* W2s = W1s + 512 * 32;       // 512k x 16n  =  8192 f
    float* As  = W2s + 512 * 16;       // 512k x 32m  = 16384 f
    float* red = As  + 512 * 32;       // 4 x 32 x 32 =  4096 f  (208 KB total)

    const int tid = threadIdx.x;
    const int b   = blockIdx.x;
    const int grp = b >> 4;            // M-group 0..7
    const int m0  = grp * 32;
    const int nT  = b & 15;            // 16 N-tiles
    const int n0w = nT * 32;           // phases A,B (N=512)
    const int n0c = nT * 16;           // phase C   (N=256)

    unsigned* arr = &g_arr[grp * 32];
    unsigned* gen = &g_gen[grp * 32];

    // ---- stage weight slices into SMEM ([k][n] layout)
    for (int e = tid; e < 32 * 256; e += 256) {
        const int n = e >> 8, k = e & 255;
        W0s[k * 32 + n] = fw0[(size_t)(n0w + n) * 256 + k];
    }
    for (int e = tid; e < 32 * 512; e += 256) {
        const int n = e >> 9, k = e & 511;
        W1s[k * 32 + n] = fw1[(size_t)(n0w + n) * 512 + k];
    }
    for (int e = tid; e < 16 * 512; e += 256) {
        const int n = e >> 9, k = e & 511;
        W2s[k * 16 + n] = fw2[(size_t)(n0c + n) * 512 + k];
    }
    __syncthreads();

    unsigned lg = 0;
    if (tid == 0) {
        asm volatile("ld.acquire.gpu.u32 %0, [%1];" : "=r"(lg) : "l"(gen) : "memory");
    }

    float* K1 = kst;
    float* K2 = kst + BSZ * LATD;
    float* K3 = kst + 2 * BSZ * LATD;

    for (int n = 0; n < TSTEPS - 1; n++) {
        const float hh = t[n + 1] - t[n];
        const float* zn = zbuf + (size_t)n * (BSZ * LATD);
        float* znx      = zbuf + (size_t)(n + 1) * (BSZ * LATD);

        // stage 1
        phase<256, 32, 1>(zn, nullptr, 0.f, W0s, fb0, h1buf, m0, n0w, 512, As, red, 0, 0, 0, 0, 0, 0.f);
        gsync(arr, gen, lg);
        phase<512, 32, 1>(h1buf, nullptr, 0.f, W1s, fb1, h2buf, m0, n0w, 512, As, red, 0, 0, 0, 0, 0, 0.f);
        gsync(arr, gen, lg);
        phase<512, 16, 0>(h2buf, nullptr, 0.f, W2s, fb2, K1, m0, n0c, 256, As, red, 0, 0, 0, 0, 0, 0.f);
        gsync(arr, gen, lg);
        // stage 2
        phase<256, 32, 1>(zn, K1, 0.5f * hh, W0s, fb0, h1buf, m0, n0w, 512, As, red, 0, 0, 0, 0, 0, 0.f);
        gsync(arr, gen, lg);
        phase<512, 32, 1>(h1buf, nullptr, 0.f, W1s, fb1, h2buf, m0, n0w, 512, As, red, 0, 0, 0, 0, 0, 0.f);
        gsync(arr, gen, lg);
        phase<512, 16, 0>(h2buf, nullptr, 0.f, W2s, fb2, K2, m0, n0c, 256, As, red, 0, 0, 0, 0, 0, 0.f);
        gsync(arr, gen, lg);
        // stage 3
        phase<256, 32, 1>(zn, K2, 0.5f * hh, W0s, fb0, h1buf, m0, n0w, 512, As, red, 0, 0, 0, 0, 0, 0.f);
        gsync(arr, gen, lg);
        phase<512, 32, 1>(h1buf, nullptr, 0.f, W1s, fb1, h2buf, m0, n0w, 512, As, red, 0, 0, 0, 0, 0, 0.f);
        gsync(arr, gen, lg);
        phase<512, 16, 0>(h2buf, nullptr, 0.f, W2s, fb2, K3, m0, n0c, 256, As, red, 0, 0, 0, 0, 0, 0.f);
        gsync(arr, gen, lg);
        // stage 4 + fused z update
        phase<256, 32, 1>(zn, K3, hh, W0s, fb0, h1buf, m0, n0w, 512, As, red, 0, 0, 0, 0, 0, 0.f);
        gsync(arr, gen, lg);
        phase<512, 32, 1>(h1buf, nullptr, 0.f, W1s, fb1, h2buf, m0, n0w, 512, As, red, 0, 0, 0, 0, 0, 0.f);
        gsync(arr, gen, lg);
        phase<512, 16, 2>(h2buf, nullptr, 0.f, W2s, fb2, nullptr, m0, n0c, 256, As, red,
                          zn, K1, K2, K3, znx, hh);
        gsync(arr, gen, lg);
    }
}

// ---------------- encoder: fused wcat + im2col gather + GEMM ----------------
// G=1: A from y (M=768), G=2: A from x0 (M=512), G=3: A from x1 (M=256)
template<int G>
__device__ __forceinline__ float gatherA(const float* __restrict__ src, int row, int c)
{
    if (G == 1) {
        const int l = row >> 8, b = row & 255;
        if (c < 192) {
            const int i = c / 3, kk = c - 3 * i, p = l + kk - 1;
            return (p >= 0) ? src[(size_t)b * 65536 + i * 1024 + p] : 0.f;
        }
        return src[(size_t)b * 65536 + (c - 192) * 1024 + l];
    } else if (G == 2) {
        const int l = row >> 8, b = row & 255;
        if (c < 768) {
            const int i = c / 3, kk = c - 3 * i, p = l + kk - 1;
            return (p >= 0) ? src[(size_t)(p * 256 + b) * 256 + i] : 0.f;
        }
        return src[(size_t)(l * 256 + b) * 256 + (c - 768)];
    } else {
        const int b = row;
        if (c < 256)  return src[(size_t)b * 256 + c];
        if (c < 512)  return src[(size_t)(256 + b) * 256 + (c - 256)];
        return src[(size_t)b * 256 + (c - 512)];
    }
}

template<int G>
__device__ __forceinline__ float gatherW(const float* __restrict__ ew,
                                         const float* __restrict__ rw, int o, int c)
{
    if (G == 1) {
        if (c < 192) return ew[o * 192 + c];
        return rw[o * 64 + (c - 192)];
    } else if (G == 2) {
        if (c < 768) return ew[o * 768 + c];
        return rw[o * 256 + (c - 768)];
    } else {
        if (c < 256)  return ew[o * 768 + c * 3 + 1];
        if (c < 512)  return ew[o * 768 + (c - 256) * 3 + 2];
        return rw[o * 256 + (c - 512)];
    }
}

// 32x32x32 tile, 256 threads, 2x2 register tile. TANH = apply tanh epilogue.
template<int G, int TANH>
__launch_bounds__(256)
__global__ void enc_gemm(const float* __restrict__ Asrc,
                         const float* __restrict__ ew, const float* __restrict__ rw,
                         const float* __restrict__ eb, const float* __restrict__ rb,
                         float* __restrict__ C, int K)
{
    __shared__ float As[32][34];
    __shared__ float Bs[32][34];

    const int tid = threadIdx.x;
    const int tx  = tid & 15;
    const int ty  = tid >> 4;
    const int m0  = blockIdx.y * 32;
    const int n0  = blockIdx.x * 32;

    const int ar = tid >> 3;           // 0..31
    const int ak = (tid & 7) * 4;      // 0,4,..,28

    float acc[2][2] = {{0.f, 0.f}, {0.f, 0.f}};

    for (int k0 = 0; k0 < K; k0 += 32) {
#pragma unroll
        for (int j = 0; j < 4; j++) {
            As[ak + j][ar] = gatherA<G>(Asrc, m0 + ar, k0 + ak + j);
            Bs[ak + j][ar] = gatherW<G>(ew, rw, n0 + ar, k0 + ak + j);
        }
        __syncthreads();
#pragma unroll
        for (int k = 0; k < 32; k++) {
            const float a0 = As[k][ty * 2], a1 = As[k][ty * 2 + 1];
            const float b0 = Bs[k][tx * 2], b1 = Bs[k][tx * 2 + 1];
            acc[0][0] = fmaf(a0, b0, acc[0][0]);
            acc[0][1] = fmaf(a0, b1, acc[0][1]);
            acc[1][0] = fmaf(a1, b0, acc[1][0]);
            acc[1][1] = fmaf(a1, b1, acc[1][1]);
        }
        __syncthreads();
    }

#pragma unroll
    for (int i = 0; i < 2; i++) {
        const int m = m0 + ty * 2 + i;
#pragma unroll
        for (int j = 0; j < 2; j++) {
            const int n = n0 + tx * 2 + j;
            float v = acc[i][j] + eb[n] + rb[n];
            if (TANH) v = tanhf(v);
            C[(size_t)m * 256 + n] = v;
        }
    }
}

// ---------------- decoder GEMM: 64x64x16 tile, f32x2 inner ----------------
// EPI: 1 = bias+tanh, 0 = bias, 3 = bias + transposed store into (B,SIG,T)
template<int EPI>
__launch_bounds__(256)
__global__ void dec_gemm(const float* __restrict__ A,
                         const float* __restrict__ W,
                         const float* __restrict__ bias,
                         float* __restrict__ C,
                         int M, int N, int K)
{
    __shared__ float As[16][68];
    __shared__ float Bs[16][68];

    const int tid = threadIdx.x;
    const int tx  = tid & 15;          // 16 n-threads
    const int ty  = tid >> 4;          // 16 m-threads
    const int m0  = blockIdx.y * 64;
    const int n0  = blockIdx.x * 64;

    const int ar = tid >> 2;           // 0..63
    const int ak = (tid & 3) * 4;      // 0,4,8,12

    unsigned long long acc2[2][4];
#pragma unroll
    for (int i = 0; i < 2; i++)
#pragma unroll
        for (int j = 0; j < 4; j++) acc2[i][j] = 0ULL;

    const float* Aptr = A + (size_t)(m0 + ar) * K + ak;
    const float* Wptr = W + (size_t)(n0 + ar) * K + ak;

    for (int k0 = 0; k0 < K; k0 += 16) {
        const float4 av = *(const float4*)(Aptr + k0);
        const float4 bv = *(const float4*)(Wptr + k0);
        As[ak + 0][ar] = av.x; As[ak + 1][ar] = av.y;
        As[ak + 2][ar] = av.z; As[ak + 3][ar] = av.w;
        Bs[ak + 0][ar] = bv.x; Bs[ak + 1][ar] = bv.y;
        Bs[ak + 2][ar] = bv.z; Bs[ak + 3][ar] = bv.w;
        __syncthreads();
#pragma unroll
        for (int k = 0; k < 16; k++) {
            const ulonglong2 a2 = *(const ulonglong2*)(&As[k][ty * 4]);
            const float4 b4 = *(const float4*)(&Bs[k][tx * 4]);
            unsigned long long bb[4];
            bb[0] = pack2(b4.x); bb[1] = pack2(b4.y);
            bb[2] = pack2(b4.z); bb[3] = pack2(b4.w);
#pragma unroll
            for (int j = 0; j < 4; j++) {
                fma2(acc2[0][j], a2.x, bb[j]);
                fma2(acc2[1][j], a2.y, bb[j]);
            }
        }
        __syncthreads();
    }

#pragma unroll
    for (int i = 0; i < 2; i++) {
#pragma unroll
        for (int j = 0; j < 4; j++) {
            float lo, hi;
            unpack2(lo, hi, acc2[i][j]);
            const int n = n0 + tx * 4 + j;
            const float bval = bias[n];
#pragma unroll
            for (int half = 0; half < 2; half++) {
                const int m = m0 + ty * 4 + 2 * i + half;
                float v = (half == 0 ? lo : hi) + bval;
                if (EPI == 1) v = tanhf(v);
                if (EPI == 3) {
                    const int tt = m >> 8;
                    const int bb2 = m & 255;
                    C[(size_t)bb2 * (SIG * TSTEPS) + (size_t)n * TSTEPS + tt] = v;
                } else {
                    C[(size_t)m * N + n] = v;
                }
            }
        }
    }
}

extern "C" void kernel_launch(void* const* d_in, const int* in_sizes, int n_in,
                              void* d_out, int out_size)
{
    const float* y   = (const float*)d_in[0];
    const float* t   = (const float*)d_in[1];
    const float* ew0 = (const float*)d_in[2];
    const float* eb0 = (const float*)d_in[3];
    const float* rw0 = (const float*)d_in[4];
    const float* rb0 = (const float*)d_in[5];
    const float* ew1 = (const float*)d_in[6];
    const float* eb1 = (const float*)d_in[7];
    const float* rw1 = (const float*)d_in[8];
    const float* rb1 = (const float*)d_in[9];
    const float* ew2 = (const float*)d_in[10];
    const float* eb2 = (const float*)d_in[11];
    const float* rw2 = (const float*)d_in[12];
    const float* rb2 = (const float*)d_in[13];
    const float* fw0 = (const float*)d_in[14];
    const float* fb0 = (const float*)d_in[15];
    const float* fw1 = (const float*)d_in[16];
    const float* fb1 = (const float*)d_in[17];
    const float* fw2 = (const float*)d_in[18];
    const float* fb2 = (const float*)d_in[19];
    const float* dw0 = (const float*)d_in[20];
    const float* db0 = (const float*)d_in[21];
    const float* dw1 = (const float*)d_in[22];
    const float* db1 = (const float*)d_in[23];
    const float* dw2 = (const float*)d_in[24];
    const float* db2 = (const float*)d_in[25];
    float* out = (float*)d_out;

    float *zbuf, *h1, *h2, *kst, *x0, *x1, *hd1, *hd2;
    cudaGetSymbolAddress((void**)&zbuf, g_z);
    cudaGetSymbolAddress((void**)&h1,  g_h1);
    cudaGetSymbolAddress((void**)&h2,  g_h2);
    cudaGetSymbolAddress((void**)&kst, g_kst);
    cudaGetSymbolAddress((void**)&x0,  g_x0);
    cudaGetSymbolAddress((void**)&x1,  g_x1);
    cudaGetSymbolAddress((void**)&hd1, g_hd1);
    cudaGetSymbolAddress((void**)&hd2, g_hd2);

    // ---------- encoder: 3 fused gather-GEMMs ----------
    { dim3 g(8, 24); enc_gemm<1, 1><<<g, 256>>>(y,  ew0, rw0, eb0, rb0, x0, 256);  }
    { dim3 g(8, 16); enc_gemm<2, 1><<<g, 256>>>(x0, ew1, rw1, eb1, rb1, x1, 1024); }
    { dim3 g(8, 8);  enc_gemm<3, 0><<<g, 256>>>(x1, ew2, rw2, eb2, rb2, zbuf, 768);}

    // ---------- RK4 ODE: one persistent kernel, group-local barriers ----------
    const int smem_bytes = (256 * 32 + 512 * 32 + 512 * 16 + 512 * 32 + 4096) * 4;
    cudaFuncSetAttribute(ode_kernel, cudaFuncAttributeMaxDynamicSharedMemorySize,
                         smem_bytes);
    ode_kernel<<<NBLK, 256, smem_bytes>>>(t, fw0, fb0, fw1, fb1, fw2, fb2,
                                          zbuf, h1, h2, kst);

    // ---------- decoder over all 200 states ----------
    { dim3 g(DECH / 64, TSTEPS * BSZ / 64); dec_gemm<1><<<g, 256>>>(zbuf, dw0, db0, hd1, TSTEPS * BSZ, DECH, LATD); }
    { dim3 g(DECH / 64, TSTEPS * BSZ / 64); dec_gemm<1><<<g, 256>>>(hd1,  dw1, db1, hd2, TSTEPS * BSZ, DECH, DECH); }
    { dim3 g(SIG  / 64, TSTEPS * BSZ / 64); dec_gemm<3><<<g, 256>>>(hd2,  dw2, db2, out, TSTEPS * BSZ, SIG,  DECH); }
}

// round 5
// speedup vs baseline: 1.2909x; 1.1210x over previous
#include <cuda_runtime.h>
#include <cuda_bf16.h>
#include <math.h>

// Problem dims
#define BSZ   256
#define SIG   64
#define LATD  256
#define ENCH  256
#define DECH  512
#define RHSH  512
#define TSTEPS 200

#define NBLK   128   // persistent ODE grid, 1 block/SM
#define GRPSZ  16    // half-blocks per group
#define NGRP   16    // 16 groups x 16 batch rows

// ---------------- scratch (device globals; no allocation) ----------------
__device__ float g_z[TSTEPS * BSZ * LATD];        // pred_z
__device__ float g_h1[BSZ * RHSH];
__device__ float g_h2[BSZ * RHSH];
__device__ float g_kst[3 * BSZ * LATD];           // k1,k2,k3
__device__ float g_x0[3 * BSZ * ENCH];            // enc layer0 out, rows l*256+b
__device__ float g_x1[2 * BSZ * ENCH];            // enc layer1 out
__device__ float g_hd1[(size_t)TSTEPS * BSZ * DECH];
__device__ float g_hd2[(size_t)TSTEPS * BSZ * DECH];

// per-group barrier state (128B padding -> one L2 line per group)
__device__ unsigned g_arr[NGRP * 32];
__device__ unsigned g_gen[NGRP * 32];

// ---------------- f32x2 packed-FMA helpers ----------------
__device__ __forceinline__ void fma2(unsigned long long& d,
                                     unsigned long long a,
                                     unsigned long long b)
{
    asm("fma.rn.f32x2 %0, %1, %2, %0;" : "+l"(d) : "l"(a), "l"(b));
}
__device__ __forceinline__ unsigned long long pack2(float x)
{
    unsigned long long r;
    asm("mov.b64 %0, {%1, %1};" : "=l"(r) : "f"(x));
    return r;
}
__device__ __forceinline__ void unpack2(float& lo, float& hi, unsigned long long v)
{
    asm("mov.b64 {%0, %1}, %2;" : "=f"(lo), "=f"(hi) : "l"(v));
}

__device__ __forceinline__ void hbar(int barid)
{
    asm volatile("bar.sync %0, 128;" :: "r"(barid) : "memory");
}

// ---------------- half-block group barrier (16 half-blocks) ----------------
__device__ __forceinline__ void gsync(unsigned* arr, unsigned* gen,
                                      unsigned& lg, int barid, int tid_h)
{
    hbar(barid);
    if (tid_h == 0) {
        unsigned ticket;
        asm volatile("atom.acq_rel.gpu.add.u32 %0, [%1], 1;"
                     : "=r"(ticket) : "l"(arr) : "memory");
        const unsigned target = lg + 1;
        if ((ticket & (GRPSZ - 1)) == GRPSZ - 1) {
            asm volatile("st.release.gpu.u32 [%0], %1;"
                         :: "l"(gen), "r"(target) : "memory");
        } else {
            unsigned g;
            do {
                asm volatile("ld.acquire.gpu.u32 %0, [%1];"
                             : "=r"(g) : "l"(gen) : "memory");
            } while ((int)(g - target) < 0);
        }
        lg = target;
    }
    hbar(barid);
}

// ---------------- half-block GEMM phase ----------------
// C[m0:m0+16, n0:n0+NW] = epi( (A + c*Kadd)[m0:m0+16, :] @ Ws^T + bias )
// Ws: SMEM weight slice, [k][n] layout (stride NW). 128 threads:
// 4 warps = 4 K-splits; per warp 32 lanes with 4m x TN register tiles (f32x2).
// EPI: 0 = bias, 1 = bias+tanh, 2 = RK4 combine (v is k4; writes zout)
template<int KDIM, int NW, int EPI>
__device__ __forceinline__ void phase(
    const float* __restrict__ Aop, const float* __restrict__ Kadd, float c,
    const float* __restrict__ Ws, const float* __restrict__ biasS,
    float* __restrict__ Cout, int m0, int n0, int Nfull,
    float* __restrict__ As, float* __restrict__ red,
    int tid_h, int barid,
    const float* __restrict__ zn, const float* __restrict__ Kk1,
    const float* __restrict__ Kk2, const float* __restrict__ Kk3,
    float* __restrict__ zout, float hh)
{
    // ---- stage A tile (16 rows x KDIM) into As[k][m] (stride 16), L2-only
    {
        const int m  = tid_h & 15;
        const int kq = tid_h >> 4;   // 0..7
        const float* arow = Aop + (size_t)(m0 + m) * KDIM;
        const float* krow = Kadd ? Kadd + (size_t)(m0 + m) * KDIM : nullptr;
#pragma unroll
        for (int it = 0; it < KDIM / 32; ++it) {
            const int k = (it * 8 + kq) * 4;
            float4 av = __ldcg((const float4*)(arow + k));
            if (Kadd) {
                const float4 kv = __ldcg((const float4*)(krow + k));
                av.x += c * kv.x; av.y += c * kv.y;
                av.z += c * kv.z; av.w += c * kv.w;
            }
            As[(k + 0) * 16 + m] = av.x;
            As[(k + 1) * 16 + m] = av.y;
            As[(k + 2) * 16 + m] = av.z;
            As[(k + 3) * 16 + m] = av.w;
        }
    }
    hbar(barid);

    constexpr int TN = NW / 8;    // 4 or 2
    constexpr int KG = KDIM / 4;
    const int g    = tid_h >> 5;  // warp = K-split 0..3
    const int lane = tid_h & 31;
    const int tm   = lane >> 3;   // 0..3
    const int tn   = lane & 7;    // 0..7

    unsigned long long acc2[2][TN];
#pragma unroll
    for (int i = 0; i < 2; i++)
#pragma unroll
        for (int j = 0; j < TN; j++) acc2[i][j] = 0ULL;

    const float* Ag = As + g * KG * 16 + tm * 4;
    const float* Wg = Ws + g * KG * NW + tn * TN;
#pragma unroll 4
    for (int k = 0; k < KG; ++k) {
        const ulonglong2 a2 = *(const ulonglong2*)(Ag + k * 16);
        unsigned long long bb[TN];
        if constexpr (TN == 4) {
            const float4 b4 = *(const float4*)(Wg + k * NW);
            bb[0] = pack2(b4.x); bb[1] = pack2(b4.y);
            bb[2] = pack2(b4.z); bb[3] = pack2(b4.w);
        } else {
            const float2 b2 = *(const float2*)(Wg + k * NW);
            bb[0] = pack2(b2.x); bb[1] = pack2(b2.y);
        }
#pragma unroll
        for (int j = 0; j < TN; ++j) {
            fma2(acc2[0][j], a2.x, bb[j]);
            fma2(acc2[1][j], a2.y, bb[j]);
        }
    }

    // ---- cross-warp K reduction via smem
#pragma unroll
    for (int i = 0; i < 2; ++i)
#pragma unroll
        for (int j = 0; j < TN; ++j) {
            float lo, hi;
            unpack2(lo, hi, acc2[i][j]);
            red[g * (16 * NW) + (tm * 4 + 2 * i)     * NW + tn * TN + j] = lo;
            red[g * (16 * NW) + (tm * 4 + 2 * i + 1) * NW + tn * TN + j] = hi;
        }
    hbar(barid);

    for (int e = tid_h; e < 16 * NW; e += 128) {
        const int m = e / NW, n = e % NW;
        float v = red[m * NW + n] + red[(16 * NW) + m * NW + n] +
                  red[2 * (16 * NW) + m * NW + n] + red[3 * (16 * NW) + m * NW + n];
        v += biasS[n];
        if (EPI == 1) v = tanhf(v);
        if (EPI == 2) {
            const size_t idx = (size_t)(m0 + m) * Nfull + n0 + n;
            zout[idx] = __ldcg(zn + idx) +
                        hh * (1.f / 6.f) *
                        (__ldcg(Kk1 + idx) + 2.f * __ldcg(Kk2 + idx) +
                         2.f * __ldcg(Kk3 + idx) + v);
        } else {
            Cout[(size_t)(m0 + m) * Nfull + n0 + n] = v;
        }
    }
    // no trailing bar: the following gsync() provides it
}

// ---------------- persistent ODE kernel: 2 independent halves per block ----
__global__ void __launch_bounds__(256, 1) ode_kernel(
    const float* __restrict__ t,
    const float* __restrict__ fw0, const float* __restrict__ fb0,
    const float* __restrict__ fw1, const float* __restrict__ fb1,
    const float* __restrict__ fw2, const float* __restrict__ fb2,
    float* __restrict__ zbuf, float* __restrict__ h1buf,
    float* __restrict__ h2buf, float* __restrict__ kst)
{
    extern __shared__ float smem[];
    float* W0s  = smem;                  // 256k x 32n = 8192 f
    float* W1s  = W0s + 256 * 32;        // 512k x 32n = 16384 f
    float* W2s  = W1s + 512 * 32;        // 512k x 16n = 8192 f
    float* As0  = W2s + 512 * 16;        // 512k x 16m = 8192 f
    float* As1  = As0 + 512 * 16;        // 8192 f
    float* red0 = As1 + 512 * 16;        // 4 x 16 x 32 = 2048 f
    float* red1 = red0 + 2048;           // 2048 f
    float* biasS = red1 + 2048;          // 96 f   (total ~213 KB)

    const int tid = threadIdx.x;
    const int b   = blockIdx.x;
    const int nT  = b & 15;
    const int n0w = nT * 32;             // phases A,B (N=512)
    const int n0c = nT * 16;             // phase C   (N=256)
    const int row = b >> 4;              // 0..7

    // ---- stage shared weight slices + bias into SMEM (full block)
    for (int e = tid; e < 32 * 256; e += 256) {
        const int n = e >> 8, k = e & 255;
        W0s[k * 32 + n] = fw0[(size_t)(n0w + n) * 256 + k];
    }
    for (int e = tid; e < 32 * 512; e += 256) {
        const int n = e >> 9, k = e & 511;
        W1s[k * 32 + n] = fw1[(size_t)(n0w + n) * 512 + k];
    }
    for (int e = tid; e < 16 * 512; e += 256) {
        const int n = e >> 9, k = e & 511;
        W2s[k * 16 + n] = fw2[(size_t)(n0c + n) * 512 + k];
    }
    if (tid < 32)                   biasS[tid]      = fb0[n0w + tid];
    else if (tid < 64)              biasS[tid]      = fb1[n0w + tid - 32];
    else if (tid < 80)              biasS[tid]      = fb2[n0c + tid - 64];
    __syncthreads();

    // ---- half-block identity
    const int h     = tid >> 7;          // 0 or 1
    const int tid_h = tid & 127;
    const int barid = h + 1;             // named barriers 1 / 2
    // half 0: row groups; half 1: diagonal groups (decorrelated SM sets)
    const int grp = (h == 0) ? row : (8 + ((row + nT) & 7));
    const int m0  = grp * 16;

    unsigned* arr = &g_arr[grp * 32];
    unsigned* gen = &g_gen[grp * 32];
    float* As  = (h == 0) ? As0  : As1;
    float* red = (h == 0) ? red0 : red1;

    unsigned lg = 0;
    if (tid_h == 0) {
        asm volatile("ld.acquire.gpu.u32 %0, [%1];" : "=r"(lg) : "l"(gen) : "memory");
    }

    float* K1 = kst;
    float* K2 = kst + BSZ * LATD;
    float* K3 = kst + 2 * BSZ * LATD;

    for (int n = 0; n < TSTEPS - 1; n++) {
        const float hh = __ldg(&t[n + 1]) - __ldg(&t[n]);
        const float* zn = zbuf + (size_t)n * (BSZ * LATD);
        float* znx      = zbuf + (size_t)(n + 1) * (BSZ * LATD);

        // stage 1
        phase<256, 32, 1>(zn, nullptr, 0.f, W0s, biasS, h1buf, m0, n0w, 512, As, red, tid_h, barid, 0, 0, 0, 0, 0, 0.f);
        gsync(arr, gen, lg, barid, tid_h);
        phase<512, 32, 1>(h1buf, nullptr, 0.f, W1s, biasS + 32, h2buf, m0, n0w, 512, As, red, tid_h, barid, 0, 0, 0, 0, 0, 0.f);
        gsync(arr, gen, lg, barid, tid_h);
        phase<512, 16, 0>(h2buf, nullptr, 0.f, W2s, biasS + 64, K1, m0, n0c, 256, As, red, tid_h, barid, 0, 0, 0, 0, 0, 0.f);
        gsync(arr, gen, lg, barid, tid_h);
        // stage 2
        phase<256, 32, 1>(zn, K1, 0.5f * hh, W0s, biasS, h1buf, m0, n0w, 512, As, red, tid_h, barid, 0, 0, 0, 0, 0, 0.f);
        gsync(arr, gen, lg, barid, tid_h);
        phase<512, 32, 1>(h1buf, nullptr, 0.f, W1s, biasS + 32, h2buf, m0, n0w, 512, As, red, tid_h, barid, 0, 0, 0, 0, 0, 0.f);
        gsync(arr, gen, lg, barid, tid_h);
        phase<512, 16, 0>(h2buf, nullptr, 0.f, W2s, biasS + 64, K2, m0, n0c, 256, As, red, tid_h, barid, 0, 0, 0, 0, 0, 0.f);
        gsync(arr, gen, lg, barid, tid_h);
        // stage 3
        phase<256, 32, 1>(zn, K2, 0.5f * hh, W0s, biasS, h1buf, m0, n0w, 512, As, red, tid_h, barid, 0, 0, 0, 0, 0, 0.f);
        gsync(arr, gen, lg, barid, tid_h);
        phase<512, 32, 1>(h1buf, nullptr, 0.f, W1s, biasS + 32, h2buf, m0, n0w, 512, As, red, tid_h, barid, 0, 0, 0, 0, 0, 0.f);
        gsync(arr, gen, lg, barid, tid_h);
        phase<512, 16, 0>(h2buf, nullptr, 0.f, W2s, biasS + 64, K3, m0, n0c, 256, As, red, tid_h, barid, 0, 0, 0, 0, 0, 0.f);
        gsync(arr, gen, lg, barid, tid_h);
        // stage 4 + fused z update
        phase<256, 32, 1>(zn, K3, hh, W0s, biasS, h1buf, m0, n0w, 512, As, red, tid_h, barid, 0, 0, 0, 0, 0, 0.f);
        gsync(arr, gen, lg, barid, tid_h);
        phase<512, 32, 1>(h1buf, nullptr, 0.f, W1s, biasS + 32, h2buf, m0, n0w, 512, As, red, tid_h, barid, 0, 0, 0, 0, 0, 0.f);
        gsync(arr, gen, lg, barid, tid_h);
        phase<512, 16, 2>(h2buf, nullptr, 0.f, W2s, biasS + 64, nullptr, m0, n0c, 256, As, red, tid_h, barid,
                          zn, K1, K2, K3, znx, hh);
        gsync(arr, gen, lg, barid, tid_h);
    }
}

// ---------------- encoder: fused wcat + im2col gather + GEMM ----------------
template<int G>
__device__ __forceinline__ float gatherA(const float* __restrict__ src, int row, int c)
{
    if (G == 1) {
        const int l = row >> 8, b = row & 255;
        if (c < 192) {
            const int i = c / 3, kk = c - 3 * i, p = l + kk - 1;
            return (p >= 0) ? src[(size_t)b * 65536 + i * 1024 + p] : 0.f;
        }
        return src[(size_t)b * 65536 + (c - 192) * 1024 + l];
    } else if (G == 2) {
        const int l = row >> 8, b = row & 255;
        if (c < 768) {
            const int i = c / 3, kk = c - 3 * i, p = l + kk - 1;
            return (p >= 0) ? src[(size_t)(p * 256 + b) * 256 + i] : 0.f;
        }
        return src[(size_t)(l * 256 + b) * 256 + (c - 768)];
    } else {
        const int b = row;
        if (c < 256)  return src[(size_t)b * 256 + c];
        if (c < 512)  return src[(size_t)(256 + b) * 256 + (c - 256)];
        return src[(size_t)b * 256 + (c - 512)];
    }
}

template<int G>
__device__ __forceinline__ float gatherW(const float* __restrict__ ew,
                                         const float* __restrict__ rw, int o, int c)
{
    if (G == 1) {
        if (c < 192) return ew[o * 192 + c];
        return rw[o * 64 + (c - 192)];
    } else if (G == 2) {
        if (c < 768) return ew[o * 768 + c];
        return rw[o * 256 + (c - 768)];
    } else {
        if (c < 256)  return ew[o * 768 + c * 3 + 1];
        if (c < 512)  return ew[o * 768 + (c - 256) * 3 + 2];
        return rw[o * 256 + (c - 512)];
    }
}

template<int G, int TANH>
__launch_bounds__(256)
__global__ void enc_gemm(const float* __restrict__ Asrc,
                         const float* __restrict__ ew, const float* __restrict__ rw,
                         const float* __restrict__ eb, const float* __restrict__ rb,
                         float* __restrict__ C, int K)
{
    __shared__ float As[32][34];
    __shared__ float Bs[32][34];

    const int tid = threadIdx.x;
    const int tx  = tid & 15;
    const int ty  = tid >> 4;
    const int m0  = blockIdx.y * 32;
    const int n0  = blockIdx.x * 32;

    const int ar = tid >> 3;
    const int ak = (tid & 7) * 4;

    float acc[2][2] = {{0.f, 0.f}, {0.f, 0.f}};

    for (int k0 = 0; k0 < K; k0 += 32) {
#pragma unroll
        for (int j = 0; j < 4; j++) {
            As[ak + j][ar] = gatherA<G>(Asrc, m0 + ar, k0 + ak + j);
            Bs[ak + j][ar] = gatherW<G>(ew, rw, n0 + ar, k0 + ak + j);
        }
        __syncthreads();
#pragma unroll
        for (int k = 0; k < 32; k++) {
            const float a0 = As[k][ty * 2], a1 = As[k][ty * 2 + 1];
            const float b0 = Bs[k][tx * 2], b1 = Bs[k][tx * 2 + 1];
            acc[0][0] = fmaf(a0, b0, acc[0][0]);
            acc[0][1] = fmaf(a0, b1, acc[0][1]);
            acc[1][0] = fmaf(a1, b0, acc[1][0]);
            acc[1][1] = fmaf(a1, b1, acc[1][1]);
        }
        __syncthreads();
    }

#pragma unroll
    for (int i = 0; i < 2; i++) {
        const int m = m0 + ty * 2 + i;
#pragma unroll
        for (int j = 0; j < 2; j++) {
            const int n = n0 + tx * 2 + j;
            float v = acc[i][j] + eb[n] + rb[n];
            if (TANH) v = tanhf(v);
            C[(size_t)m * 256 + n] = v;
        }
    }
}

// ---------------- decoder GEMM: 64x64x16 tile, f32x2 inner ----------------
template<int EPI>
__launch_bounds__(256)
__global__ void dec_gemm(const float* __restrict__ A,
                         const float* __restrict__ W,
                         const float* __restrict__ bias,
                         float* __restrict__ C,
                         int M, int N, int K)
{
    __shared__ float As[16][68];
    __shared__ float Bs[16][68];

    const int tid = threadIdx.x;
    const int tx  = tid & 15;
    const int ty  = tid >> 4;
    const int m0  = blockIdx.y * 64;
    const int n0  = blockIdx.x * 64;

    const int ar = tid >> 2;
    const int ak = (tid & 3) * 4;

    unsigned long long acc2[2][4];
#pragma unroll
    for (int i = 0; i < 2; i++)
#pragma unroll
        for (int j = 0; j < 4; j++) acc2[i][j] = 0ULL;

    const float* Aptr = A + (size_t)(m0 + ar) * K + ak;
    const float* Wptr = W + (size_t)(n0 + ar) * K + ak;

    for (int k0 = 0; k0 < K; k0 += 16) {
        const float4 av = *(const float4*)(Aptr + k0);
        const float4 bv = *(const float4*)(Wptr + k0);
        As[ak + 0][ar] = av.x; As[ak + 1][ar] = av.y;
        As[ak + 2][ar] = av.z; As[ak + 3][ar] = av.w;
        Bs[ak + 0][ar] = bv.x; Bs[ak + 1][ar] = bv.y;
        Bs[ak + 2][ar] = bv.z; Bs[ak + 3][ar] = bv.w;
        __syncthreads();
#pragma unroll
        for (int k = 0; k < 16; k++) {
            const ulonglong2 a2 = *(const ulonglong2*)(&As[k][ty * 4]);
            const float4 b4 = *(const float4*)(&Bs[k][tx * 4]);
            unsigned long long bb[4];
            bb[0] = pack2(b4.x); bb[1] = pack2(b4.y);
            bb[2] = pack2(b4.z); bb[3] = pack2(b4.w);
#pragma unroll
            for (int j = 0; j < 4; j++) {
                fma2(acc2[0][j], a2.x, bb[j]);
                fma2(acc2[1][j], a2.y, bb[j]);
            }
        }
        __syncthreads();
    }

#pragma unroll
    for (int i = 0; i < 2; i++) {
#pragma unroll
        for (int j = 0; j < 4; j++) {
            float lo, hi;
            unpack2(lo, hi, acc2[i][j]);
            const int n = n0 + tx * 4 + j;
            const float bval = bias[n];
#pragma unroll
            for (int half = 0; half < 2; half++) {
                const int m = m0 + ty * 4 + 2 * i + half;
                float v = (half == 0 ? lo : hi) + bval;
                if (EPI == 1) v = tanhf(v);
                if (EPI == 3) {
                    const int tt = m >> 8;
                    const int bb2 = m & 255;
                    C[(size_t)bb2 * (SIG * TSTEPS) + (size_t)n * TSTEPS + tt] = v;
                } else {
                    C[(size_t)m * N + n] = v;
                }
            }
        }
    }
}

extern "C" void kernel_launch(void* const* d_in, const int* in_sizes, int n_in,
                              void* d_out, int out_size)
{
    const float* y   = (const float*)d_in[0];
    const float* t   = (const float*)d_in[1];
    const float* ew0 = (const float*)d_in[2];
    const float* eb0 = (const float*)d_in[3];
    const float* rw0 = (const float*)d_in[4];
    const float* rb0 = (const float*)d_in[5];
    const float* ew1 = (const float*)d_in[6];
    const float* eb1 = (const float*)d_in[7];
    const float* rw1 = (const float*)d_in[8];
    const float* rb1 = (const float*)d_in[9];
    const float* ew2 = (const float*)d_in[10];
    const float* eb2 = (const float*)d_in[11];
    const float* rw2 = (const float*)d_in[12];
    const float* rb2 = (const float*)d_in[13];
    const float* fw0 = (const float*)d_in[14];
    const float* fb0 = (const float*)d_in[15];
    const float* fw1 = (const float*)d_in[16];
    const float* fb1 = (const float*)d_in[17];
    const float* fw2 = (const float*)d_in[18];
    const float* fb2 = (const float*)d_in[19];
    const float* dw0 = (const float*)d_in[20];
    const float* db0 = (const float*)d_in[21];
    const float* dw1 = (const float*)d_in[22];
    const float* db1 = (const float*)d_in[23];
    const float* dw2 = (const float*)d_in[24];
    const float* db2 = (const float*)d_in[25];
    float* out = (float*)d_out;

    float *zbuf, *h1, *h2, *kst, *x0, *x1, *hd1, *hd2;
    cudaGetSymbolAddress((void**)&zbuf, g_z);
    cudaGetSymbolAddress((void**)&h1,  g_h1);
    cudaGetSymbolAddress((void**)&h2,  g_h2);
    cudaGetSymbolAddress((void**)&kst, g_kst);
    cudaGetSymbolAddress((void**)&x0,  g_x0);
    cudaGetSymbolAddress((void**)&x1,  g_x1);
    cudaGetSymbolAddress((void**)&hd1, g_hd1);
    cudaGetSymbolAddress((void**)&hd2, g_hd2);

    // ---------- encoder: 3 fused gather-GEMMs ----------
    { dim3 g(8, 24); enc_gemm<1, 1><<<g, 256>>>(y,  ew0, rw0, eb0, rb0, x0, 256);  }
    { dim3 g(8, 16); enc_gemm<2, 1><<<g, 256>>>(x0, ew1, rw1, eb1, rb1, x1, 1024); }
    { dim3 g(8, 8);  enc_gemm<3, 0><<<g, 256>>>(x1, ew2, rw2, eb2, rb2, zbuf, 768);}

    // ---------- RK4 ODE: one persistent kernel, 2 independent halves/SM ----------
    const int smem_bytes = (256 * 32 + 512 * 32 + 512 * 16 +
                            2 * 512 * 16 + 2 * 2048 + 96) * 4;
    cudaFuncSetAttribute(ode_kernel, cudaFuncAttributeMaxDynamicSharedMemorySize,
                         smem_bytes);
    ode_kernel<<<NBLK, 256, smem_bytes>>>(t, fw0, fb0, fw1, fb1, fw2, fb2,
                                          zbuf, h1, h2, kst);

    // ---------- decoder over all 200 states ----------
    { dim3 g(DECH / 64, TSTEPS * BSZ / 64); dec_gemm<1><<<g, 256>>>(zbuf, dw0, db0, hd1, TSTEPS * BSZ, DECH, LATD); }
    { dim3 g(DECH / 64, TSTEPS * BSZ / 64); dec_gemm<1><<<g, 256>>>(hd1,  dw1, db1, hd2, TSTEPS * BSZ, DECH, DECH); }
    { dim3 g(SIG  / 64, TSTEPS * BSZ / 64); dec_gemm<3><<<g, 256>>>(hd2,  dw2, db2, out, TSTEPS * BSZ, SIG,  DECH); }
}